// round 14
// baseline (speedup 1.0000x reference)
#include <cuda_runtime.h>
#include <cstdint>

// -------------------------------------------------------------------------
// SimpleESN, round 13.  Occupancy doubled: 1024 threads / 32 warps per CTA.
//  - Each warp owns a private 64-k slice + private 512B-chunk cp.async ring
//    (3 slots, distance 2). Thread accumulates 4 cols x 4 batches -> acc
//    fits in 16 regs under __launch_bounds__(1024,1).
//  - W re-tiled as k-pairs [kp][kk][c]: every h/w LDS.128 = one 128B bank
//    row = 1 wavefront.
//  - Dataflow sync: 32 slice counters, 4 producers each (target = 4t),
//    one acquire-poll per warp per step. 3-way h buffer (WAR-safe).
//  - Input projection precomputed into g_u[t][n][b]; hot loop u = 1 LDG.
// -------------------------------------------------------------------------

namespace {
constexpr int B_      = 16;
constexpr int T_      = 2048;
constexpr int F_      = 128;
constexpr int U_      = 2048;
constexpr int GRID    = 128;
constexpr int THREADS = 1024;
constexpr int COLS    = 16;
constexpr int NCHUNK  = 8;            // 8 chunks x 8 k per warp slice
constexpr int CHF     = 128;          // floats per chunk (8 k x 16 b)
constexpr int SLICE   = 1024;         // floats per warp slice (64 k x 16 b)
constexpr int BST     = 18;
constexpr int REDW    = COLS * BST;   // 288 floats per warp partial
constexpr int NZCAP   = 16;
}

// big scratch: precomputed input projection [t][n][b]
__device__ float g_u[T_ * U_ * B_];
// h triple buffer; within slice: [chunk8][kpair4][kk2*16b]
__device__ __align__(16) float g_h[3][U_ * B_];
__device__ unsigned g_cnt[32 * 32];   // 32 slice counters, 128B apart
__device__ unsigned g_ticket = 0;
// nonzero lists of input kernel columns
__device__ int   g_nzc[U_];
__device__ int   g_nzf[U_ * NZCAP];
__device__ float g_nzw[U_ * NZCAP];

struct SmemLayout {
  float Ws[(U_ / 2) * 32];   // 131072 B  [kp][kk*16+c]
  float sbuf[32][3][CHF];    //  49152 B  warp-private cp.async rings
  float red[32 * REDW];      //  36864 B  warp partials
  float wout_s[COLS];
  float ybuf[COLS * B_];
  unsigned base;
};
static_assert(sizeof(SmemLayout) <= 227 * 1024, "smem");

using u64 = unsigned long long;

__device__ __forceinline__ unsigned ld_acq(unsigned* p) {
  unsigned v;
  asm volatile("ld.acquire.gpu.global.u32 %0, [%1];" : "=r"(v) : "l"(p) : "memory");
  return v;
}
__device__ __forceinline__ void red_rel_add(unsigned* p) {
  asm volatile("red.release.gpu.global.add.u32 [%0], 1;" :: "l"(p) : "memory");
}
__device__ __forceinline__ void cpa16(uint32_t dst, const float* src) {
  asm volatile("cp.async.cg.shared.global [%0], [%1], 16;"
               :: "r"(dst), "l"(src) : "memory");
}
__device__ __forceinline__ u64 splat2(float w) {
  u64 r;
  asm("mov.b64 %0, {%1, %1};" : "=l"(r) : "r"(__float_as_uint(w)));
  return r;
}
__device__ __forceinline__ void fmax2(u64& a, u64 h, u64 w) {
  asm("fma.rn.f32x2 %0, %1, %2, %0;" : "+l"(a) : "l"(h), "l"(w));
}
__device__ __forceinline__ u64 addx2(u64 a, u64 b) {
  u64 r;
  asm("add.rn.f32x2 %0, %1, %2;" : "=l"(r) : "l"(a), "l"(b));
  return r;
}

// ---- setup kernel 1: nonzero lists per input-kernel column ----
__global__ void nz_kernel(const float* __restrict__ kern) {
  int n = blockIdx.x * blockDim.x + threadIdx.x;
  if (n >= U_) return;
  int cnt = 0;
  for (int f = 0; f < F_; ++f) {
    float v = kern[f * U_ + n];
    if (v != 0.f) {
      if (cnt < NZCAP) { g_nzw[n * NZCAP + cnt] = v; g_nzf[n * NZCAP + cnt] = f; }
      ++cnt;
    }
  }
  g_nzc[n] = cnt;
}

// ---- setup kernel 2: u[t][n][b] = bias[n] + sum_nz x[b][t][f]*w ----
__global__ void __launch_bounds__(512) uproj_kernel(
    const float* __restrict__ x, const float* __restrict__ kern,
    const float* __restrict__ bias) {
  __shared__ float sx[F_ * 20];  // [f][b], stride 20
  const int t = blockIdx.x;
  for (int i = threadIdx.x; i < B_ * F_; i += blockDim.x) {
    int b = i >> 7, f = i & 127;
    sx[f * 20 + b] = x[(b * T_ + t) * F_ + f];
  }
  __syncthreads();
  for (int it = threadIdx.x; it < U_ * 4; it += blockDim.x) {
    int n = it >> 2, bq = it & 3;
    float bs = bias[n];
    float4 acc = make_float4(bs, bs, bs, bs);
    int cnt = g_nzc[n];
    if (cnt <= NZCAP) {
      for (int i2 = 0; i2 < cnt; ++i2) {
        int f = g_nzf[n * NZCAP + i2];
        float w = g_nzw[n * NZCAP + i2];
        float4 xv = *reinterpret_cast<const float4*>(&sx[f * 20 + bq * 4]);
        acc.x += xv.x * w; acc.y += xv.y * w;
        acc.z += xv.z * w; acc.w += xv.w * w;
      }
    } else {
      for (int f = 0; f < F_; ++f) {
        float w = kern[f * U_ + n];
        float4 xv = *reinterpret_cast<const float4*>(&sx[f * 20 + bq * 4]);
        acc.x += xv.x * w; acc.y += xv.y * w;
        acc.z += xv.z * w; acc.w += xv.w * w;
      }
    }
    *reinterpret_cast<float4*>(&g_u[t * (U_ * B_) + n * B_ + bq * 4]) = acc;
  }
}

// ---- main persistent kernel ----
__global__ void __launch_bounds__(THREADS, 1) esn_kernel(
    const float* __restrict__ W,     // [U,U]
    const float* __restrict__ wout,  // [U,1]
    const float* __restrict__ bout,  // [1]
    float* __restrict__ out)         // [B,1]
{
  extern __shared__ unsigned char smem_raw[];
  SmemLayout& s = *reinterpret_cast<SmemLayout*>(smem_raw);
  const int tid  = threadIdx.x;
  const int n0   = blockIdx.x * COLS;
  const int lane = tid & 31;
  const int wrp  = tid >> 5;          // 0..31 = consumed slice id
  const int kk   = lane & 1;          // k parity within k-pair
  const int bq   = (lane >> 1) & 3;   // batch quad
  const int q    = (lane >> 3) & 3;   // col quad
  const int cS   = (tid >> 4) & 15;   // output col (tid<256)
  const int bS   = tid & 15;          // output batch

  if (blockIdx.x == 0 && tid < B_) out[tid] = bout[0];

  if (tid == 0) {
    unsigned tk = atomicAdd(&g_ticket, 1u);
    s.base = (tk / (unsigned)GRID) * (4u * (unsigned)T_);
  }

  // ---- W slice into smem, k-pair tiling: dst = (k>>1)*32 + (k&1)*16 + c ----
  for (int i = tid; i < U_ * COLS; i += THREADS) {
    int k = i >> 4, c = i & 15;
    s.Ws[(k >> 1) * 32 + (k & 1) * 16 + c] = W[k * U_ + n0 + c];
  }
  if (tid < COLS) s.wout_s[tid] = wout[n0 + tid];
  __syncthreads();

  const unsigned base = s.base;

  // producer store index (permuted layout), constant over t
  int pidx = 0;
  if (tid < 256) {
    const int n = n0 + cS;
    pidx = (n >> 6) * SLICE + ((n >> 3) & 7) * CHF + ((n >> 1) & 3) * 32 +
           (n & 1) * 16 + bS;
  }
  const float* uptr = g_u + (n0 + cS) * B_ + bS;

  // consumer constants
  float* const myring = &s.sbuf[wrp][0][0];
  const uint32_t rbase = (uint32_t)__cvta_generic_to_shared(myring);
  const int hoffB = kk * 16 + bq * 4;               // within-row float offset
  const float* const wbase = &s.Ws[wrp * 1024 + kk * 16 + q * 4];
  unsigned* const mycnt = &g_cnt[wrp * 32];
  unsigned* const prodcnt = &g_cnt[(blockIdx.x >> 2) * 32];

  float hval = 0.f;

  for (int t = 0; t < T_; ++t) {
    // ---- u: one coalesced load, independent of h ----
    float uval = 0.f;
    if (tid < 256) uval = __ldg(uptr + t * (U_ * B_));

    u64 acc[8];
    if (t > 0) {
      const unsigned tgt = base + 4u * (unsigned)t;
      while ((int)(ld_acq(mycnt) - tgt) < 0) {}

      const float* hsl = g_h[(t - 1) % 3] + wrp * SLICE;

      // prologue: chunks 0,1 into ring slots 0,1
      #pragma unroll
      for (int p = 0; p < 2; ++p) {
        cpa16(rbase + (unsigned)(p * CHF + lane * 4) * 4u,
              hsl + p * CHF + lane * 4);
        asm volatile("cp.async.commit_group;" ::: "memory");
      }

      #pragma unroll
      for (int j = 0; j < 8; ++j) acc[j] = 0ull;

      #pragma unroll
      for (int c = 0; c < NCHUNK; ++c) {
        if (c + 2 < NCHUNK) {            // issue chunk c+2 (slot (c+2)%3)
          int sl = (c + 2) % 3;
          cpa16(rbase + (unsigned)(sl * CHF + lane * 4) * 4u,
                hsl + (c + 2) * CHF + lane * 4);
          asm volatile("cp.async.commit_group;" ::: "memory");
        }
        const int wn = (NCHUNK - 1 - c) < 2 ? (NCHUNK - 1 - c) : 2;
        if (wn == 2)      asm volatile("cp.async.wait_group 2;" ::: "memory");
        else if (wn == 1) asm volatile("cp.async.wait_group 1;" ::: "memory");
        else              asm volatile("cp.async.wait_group 0;" ::: "memory");
        __syncwarp();

        const float* hb = myring + (c % 3) * CHF + hoffB;
        const float* wc = wbase + c * 128;
        #pragma unroll
        for (int r = 0; r < 4; ++r) {    // k = wrp*64 + c*8 + r*2 + kk
          ulonglong2 h2 = *reinterpret_cast<const ulonglong2*>(hb + r * 32);
          const float4 wv = *reinterpret_cast<const float4*>(wc + r * 32);
          u64 w0 = splat2(wv.x), w1 = splat2(wv.y);
          u64 w2 = splat2(wv.z), w3 = splat2(wv.w);
          fmax2(acc[0], h2.x, w0); fmax2(acc[1], h2.y, w0);
          fmax2(acc[2], h2.x, w1); fmax2(acc[3], h2.y, w1);
          fmax2(acc[4], h2.x, w2); fmax2(acc[5], h2.y, w2);
          fmax2(acc[6], h2.x, w3); fmax2(acc[7], h2.y, w3);
        }
        __syncwarp();
      }

      // fold kk (lane bit 0); keeps (bq, q)
      #pragma unroll
      for (int j = 0; j < 8; ++j)
        acc[j] = addx2(acc[j], __shfl_xor_sync(0xFFFFFFFFu, acc[j], 1));
      if (kk == 0) {
        #pragma unroll
        for (int cl = 0; cl < 4; ++cl) {
          float* r = &s.red[wrp * REDW + (q * 4 + cl) * BST + bq * 4];
          *reinterpret_cast<u64*>(r)     = acc[cl * 2];
          *reinterpret_cast<u64*>(r + 2) = acc[cl * 2 + 1];
        }
      }
    }
    __syncthreads();  // partials visible; also orders red WAR across steps

    if (tid < 256) {
      float sum = 0.f;
      if (t > 0) {
        const float* rp = &s.red[cS * BST + bS];
        #pragma unroll
        for (int g = 0; g < 32; ++g) sum += rp[g * REDW];
      }
      hval = tanhf(uval + sum);
      g_h[t % 3][pidx] = hval;
    }
    __syncthreads();  // h stores complete before signal
    if (tid == 0) red_rel_add(prodcnt);
  }

  // ---- readout ----
  if (tid < 256) s.ybuf[cS * B_ + bS] = hval * s.wout_s[cS];
  __syncthreads();
  if (tid < B_) {
    float y = 0.f;
    #pragma unroll
    for (int c = 0; c < COLS; ++c) y += s.ybuf[c * B_ + tid];
    atomicAdd(&out[tid], y);
  }
}

extern "C" void kernel_launch(void* const* d_in, const int* in_sizes, int n_in,
                              void* d_out, int out_size) {
  (void)in_sizes; (void)n_in; (void)out_size;
  const float* x    = (const float*)d_in[0];
  const float* kern = (const float*)d_in[1];
  const float* W    = (const float*)d_in[2];
  const float* bias = (const float*)d_in[3];
  const float* wout = (const float*)d_in[4];
  const float* bout = (const float*)d_in[5];

  nz_kernel<<<(U_ + 255) / 256, 256>>>(kern);
  uproj_kernel<<<T_, 512>>>(x, kern, bias);

  cudaFuncSetAttribute(esn_kernel, cudaFuncAttributeMaxDynamicSharedMemorySize,
                       (int)sizeof(SmemLayout));
  esn_kernel<<<GRID, THREADS, sizeof(SmemLayout)>>>(
      W, wout, bout, (float*)d_out);
}

// round 15
// speedup vs baseline: 1.2329x; 1.2329x over previous
#include <cuda_runtime.h>
#include <cstdint>

// -------------------------------------------------------------------------
// SimpleESN, round 14.  Base = round 9 (best: 10.09ms) with:
//  - 2KB staging chunks (NCHUNK=4), 2-slot ring, distance-1 prefetch:
//    halves wait_group/commit/syncwarp boundary overhead per step.
//  - BST=18 reduction stride.
//  Identical g_h layout, counters, polling (one per warp per step).
// -------------------------------------------------------------------------

namespace {
constexpr int B_      = 16;
constexpr int T_      = 2048;
constexpr int F_      = 128;
constexpr int U_      = 2048;
constexpr int GRID    = 128;
constexpr int THREADS = 512;
constexpr int COLS    = 16;
constexpr int NCHUNK  = 4;            // 4 chunks x 32 k per warp slice
constexpr int CHF     = 512;          // floats per chunk (32 k x 16 b)
constexpr int SLICE   = 2048;         // floats per warp slice
constexpr int BST     = 18;
constexpr int REDW    = COLS * BST;   // 288
constexpr int NZCAP   = 16;
}

// big scratch: precomputed input projection [t][n][b]
__device__ float g_u[T_ * U_ * B_];
// h triple buffer; within slice: [sub8][ic4][row2][g8][4]  (R9 layout)
__device__ __align__(16) float g_h[3][U_ * B_];
__device__ unsigned g_cnt[16 * 32];   // slice counters, 128B apart
__device__ unsigned g_ticket = 0;
// nonzero lists of input kernel columns
__device__ int   g_nzc[U_];
__device__ int   g_nzf[U_ * NZCAP];
__device__ float g_nzw[U_ * NZCAP];

struct SmemLayout {
  float Ws[U_ * COLS];       // 131072 B  [k][c]
  float sbuf[16][2][CHF];    //  65536 B  warp-private 2-slot rings (2KB each)
  float red[16 * REDW];      //  18432 B
  float wout_s[COLS];
  float ybuf[COLS * B_];
  unsigned base;
};
static_assert(sizeof(SmemLayout) <= 227 * 1024, "smem");

using u64 = unsigned long long;

__device__ __forceinline__ unsigned ld_acq(unsigned* p) {
  unsigned v;
  asm volatile("ld.acquire.gpu.global.u32 %0, [%1];" : "=r"(v) : "l"(p) : "memory");
  return v;
}
__device__ __forceinline__ void red_rel_add(unsigned* p) {
  asm volatile("red.release.gpu.global.add.u32 [%0], 1;" :: "l"(p) : "memory");
}
__device__ __forceinline__ void cpa16(uint32_t dst, const float* src) {
  asm volatile("cp.async.cg.shared.global [%0], [%1], 16;"
               :: "r"(dst), "l"(src) : "memory");
}
__device__ __forceinline__ u64 splat2(float w) {
  u64 r;
  asm("mov.b64 %0, {%1, %1};" : "=l"(r) : "r"(__float_as_uint(w)));
  return r;
}
__device__ __forceinline__ void fmax2(u64& a, u64 h, u64 w) {
  asm("fma.rn.f32x2 %0, %1, %2, %0;" : "+l"(a) : "l"(h), "l"(w));
}
__device__ __forceinline__ u64 addx2(u64 a, u64 b) {
  u64 r;
  asm("add.rn.f32x2 %0, %1, %2;" : "=l"(r) : "l"(a), "l"(b));
  return r;
}

// ---- setup kernel 1: nonzero lists per input-kernel column ----
__global__ void nz_kernel(const float* __restrict__ kern) {
  int n = blockIdx.x * blockDim.x + threadIdx.x;
  if (n >= U_) return;
  int cnt = 0;
  for (int f = 0; f < F_; ++f) {
    float v = kern[f * U_ + n];
    if (v != 0.f) {
      if (cnt < NZCAP) { g_nzw[n * NZCAP + cnt] = v; g_nzf[n * NZCAP + cnt] = f; }
      ++cnt;
    }
  }
  g_nzc[n] = cnt;
}

// ---- setup kernel 2: u[t][n][b] = bias[n] + sum_nz x[b][t][f]*w ----
__global__ void __launch_bounds__(512) uproj_kernel(
    const float* __restrict__ x, const float* __restrict__ kern,
    const float* __restrict__ bias) {
  __shared__ float sx[F_ * 20];  // [f][b], stride 20
  const int t = blockIdx.x;
  for (int i = threadIdx.x; i < B_ * F_; i += blockDim.x) {
    int b = i >> 7, f = i & 127;
    sx[f * 20 + b] = x[(b * T_ + t) * F_ + f];
  }
  __syncthreads();
  for (int it = threadIdx.x; it < U_ * 4; it += blockDim.x) {
    int n = it >> 2, bq = it & 3;
    float bs = bias[n];
    float4 acc = make_float4(bs, bs, bs, bs);
    int cnt = g_nzc[n];
    if (cnt <= NZCAP) {
      for (int i2 = 0; i2 < cnt; ++i2) {
        int f = g_nzf[n * NZCAP + i2];
        float w = g_nzw[n * NZCAP + i2];
        float4 xv = *reinterpret_cast<const float4*>(&sx[f * 20 + bq * 4]);
        acc.x += xv.x * w; acc.y += xv.y * w;
        acc.z += xv.z * w; acc.w += xv.w * w;
      }
    } else {
      for (int f = 0; f < F_; ++f) {
        float w = kern[f * U_ + n];
        float4 xv = *reinterpret_cast<const float4*>(&sx[f * 20 + bq * 4]);
        acc.x += xv.x * w; acc.y += xv.y * w;
        acc.z += xv.z * w; acc.w += xv.w * w;
      }
    }
    *reinterpret_cast<float4*>(&g_u[t * (U_ * B_) + n * B_ + bq * 4]) = acc;
  }
}

// ---- main persistent kernel ----
__global__ void __launch_bounds__(THREADS, 1) esn_kernel(
    const float* __restrict__ W,     // [U,U]
    const float* __restrict__ wout,  // [U,1]
    const float* __restrict__ bout,  // [1]
    float* __restrict__ out)         // [B,1]
{
  extern __shared__ unsigned char smem_raw[];
  SmemLayout& s = *reinterpret_cast<SmemLayout*>(smem_raw);
  const int tid  = threadIdx.x;
  const int n0   = blockIdx.x * COLS;
  const int lane = tid & 31;
  const int wrp  = tid >> 5;          // 0..15 = consumed slice id
  const int kk   = lane >> 3;
  const int hf   = (lane >> 2) & 1;
  const int q    = lane & 3;
  const int cS   = (tid >> 4) & 15;   // output col (tid<256)
  const int bS   = tid & 15;          // output batch

  if (blockIdx.x == 0 && tid < B_) out[tid] = bout[0];

  if (tid == 0) {
    unsigned tk = atomicAdd(&g_ticket, 1u);
    s.base = (tk / (unsigned)GRID) * (8u * (unsigned)T_);
  }

  for (int i = tid; i < U_ * COLS; i += THREADS) {
    int k = i >> 4, c = i & 15;
    s.Ws[i] = W[k * U_ + n0 + c];
  }
  if (tid < COLS) s.wout_s[tid] = wout[n0 + tid];
  __syncthreads();

  const unsigned base = s.base;

  // producer store index (permuted layout, identical to R9), constant over t
  int pidx = 0;
  if (tid < 256) {
    const int n = n0 + cS;
    pidx = (n >> 7) * SLICE + ((n >> 4) & 7) * 256 + ((n >> 2) & 3) * 64 +
           ((bS >> 2) & 1) * 32 + ((n & 3) * 2 + (bS >> 3)) * 4 + (bS & 3);
  }
  const float* uptr = g_u + (n0 + cS) * B_ + bS;

  // consumer constants
  float* const myring = &s.sbuf[wrp][0][0];
  const uint32_t rbase = (uint32_t)__cvta_generic_to_shared(myring);
  const int hoffB = (kk * 2 + hf) * 4;
  const float* const wbase = &s.Ws[(wrp * 128 + kk) * COLS + q * 4];
  unsigned* const mycnt = &g_cnt[wrp * 32];
  unsigned* const prodcnt = &g_cnt[(blockIdx.x >> 3) * 32];

  float hval = 0.f;

  for (int t = 0; t < T_; ++t) {
    // ---- u: one coalesced load, independent of h ----
    float uval = 0.f;
    if (tid < 256) uval = __ldg(uptr + t * (U_ * B_));

    float dot = 0.f;
    if (t > 0) {
      const unsigned tgt = base + 8u * (unsigned)t;
      while ((int)(ld_acq(mycnt) - tgt) < 0) {}

      const float* hsl = g_h[(t - 1) % 3] + wrp * SLICE;

      // prologue: chunk 0 into slot 0 (2KB = 4 cp.async per lane)
      #pragma unroll
      for (int j = 0; j < 4; ++j)
        cpa16(rbase + (unsigned)(j * 128 + lane * 4) * 4u,
              hsl + j * 128 + lane * 4);
      asm volatile("cp.async.commit_group;" ::: "memory");

      u64 acc[16];
      #pragma unroll
      for (int j = 0; j < 16; ++j) acc[j] = 0ull;

      #pragma unroll
      for (int c = 0; c < NCHUNK; ++c) {
        if (c + 1 < NCHUNK) {  // issue chunk c+1 into slot (c+1)&1
          const unsigned so = (unsigned)(((c + 1) & 1) * CHF) * 4u;
          const float* src = hsl + (c + 1) * CHF;
          #pragma unroll
          for (int j = 0; j < 4; ++j)
            cpa16(rbase + so + (unsigned)(j * 128 + lane * 4) * 4u,
                  src + j * 128 + lane * 4);
          asm volatile("cp.async.commit_group;" ::: "memory");
          asm volatile("cp.async.wait_group 1;" ::: "memory");
        } else {
          asm volatile("cp.async.wait_group 0;" ::: "memory");
        }
        __syncwarp();

        // chunk c = two 256-float sub-chunks in R9 layout
        #pragma unroll
        for (int half = 0; half < 2; ++half) {
          const float* hb = myring + (c & 1) * CHF + half * 256 + hoffB;
          const float* wc = wbase + (2 * c + half) * (16 * COLS);
          #pragma unroll
          for (int ic = 0; ic < 4; ++ic) {
            ulonglong2 ha  = *reinterpret_cast<const ulonglong2*>(hb + ic * 64);
            ulonglong2 hb2 = *reinterpret_cast<const ulonglong2*>(hb + ic * 64 + 32);
            const float4 wv = *reinterpret_cast<const float4*>(wc + ic * (4 * COLS));
            u64 w0 = splat2(wv.x), w1 = splat2(wv.y);
            u64 w2 = splat2(wv.z), w3 = splat2(wv.w);
            fmax2(acc[0],  ha.x,  w0); fmax2(acc[1],  ha.y,  w0);
            fmax2(acc[2],  hb2.x, w0); fmax2(acc[3],  hb2.y, w0);
            fmax2(acc[4],  ha.x,  w1); fmax2(acc[5],  ha.y,  w1);
            fmax2(acc[6],  hb2.x, w1); fmax2(acc[7],  hb2.y, w1);
            fmax2(acc[8],  ha.x,  w2); fmax2(acc[9],  ha.y,  w2);
            fmax2(acc[10], hb2.x, w2); fmax2(acc[11], hb2.y, w2);
            fmax2(acc[12], ha.x,  w3); fmax2(acc[13], ha.y,  w3);
            fmax2(acc[14], hb2.x, w3); fmax2(acc[15], hb2.y, w3);
          }
        }
        __syncwarp();  // all lanes done with slot before next-iter issue
      }

      // reduce over kk (lane bits 3,4); keeps (hf, q)
      #pragma unroll
      for (int j = 0; j < 16; ++j) {
        acc[j] = addx2(acc[j], __shfl_xor_sync(0xFFFFFFFFu, acc[j], 8));
        acc[j] = addx2(acc[j], __shfl_xor_sync(0xFFFFFFFFu, acc[j], 16));
      }
      if (kk == 0) {
        #pragma unroll
        for (int c = 0; c < 4; ++c) {
          float* r = &s.red[wrp * REDW + (4 * q + c) * BST + hf * 8];
          *reinterpret_cast<u64*>(r)     = acc[c * 4 + 0];
          *reinterpret_cast<u64*>(r + 2) = acc[c * 4 + 1];
          *reinterpret_cast<u64*>(r + 4) = acc[c * 4 + 2];
          *reinterpret_cast<u64*>(r + 6) = acc[c * 4 + 3];
        }
      }
      __syncthreads();

      if (tid < 256) {
        float sum = 0.f;
        const float* rp = &s.red[cS * BST + bS];
        #pragma unroll
        for (int g = 0; g < 16; ++g) sum += rp[g * REDW];
        dot = sum;
      }
    }

    // ---- tanh + store h ----
    if (tid < 256) {
      hval = tanhf(uval + dot);
      g_h[t % 3][pidx] = hval;
    }
    __syncthreads();
    if (tid == 0) red_rel_add(prodcnt);
  }

  // ---- readout ----
  if (tid < 256) s.ybuf[cS * B_ + bS] = hval * s.wout_s[cS];
  __syncthreads();
  if (tid < B_) {
    float y = 0.f;
    #pragma unroll
    for (int c = 0; c < COLS; ++c) y += s.ybuf[c * B_ + tid];
    atomicAdd(&out[tid], y);
  }
}

extern "C" void kernel_launch(void* const* d_in, const int* in_sizes, int n_in,
                              void* d_out, int out_size) {
  (void)in_sizes; (void)n_in; (void)out_size;
  const float* x    = (const float*)d_in[0];
  const float* kern = (const float*)d_in[1];
  const float* W    = (const float*)d_in[2];
  const float* bias = (const float*)d_in[3];
  const float* wout = (const float*)d_in[4];
  const float* bout = (const float*)d_in[5];

  nz_kernel<<<(U_ + 255) / 256, 256>>>(kern);
  uproj_kernel<<<T_, 512>>>(x, kern, bias);

  cudaFuncSetAttribute(esn_kernel, cudaFuncAttributeMaxDynamicSharedMemorySize,
                       (int)sizeof(SmemLayout));
  esn_kernel<<<GRID, THREADS, sizeof(SmemLayout)>>>(
      W, wout, bout, (float*)d_out);
}

// round 16
// speedup vs baseline: 1.2358x; 1.0023x over previous
#include <cuda_runtime.h>
#include <cstdint>

// -------------------------------------------------------------------------
// SimpleESN, round 14.  Base = round 9 (best: 10.09ms) with:
//  - 2KB staging chunks (NCHUNK=4), 2-slot ring, distance-1 prefetch:
//    halves wait_group/commit/syncwarp boundary overhead per step.
//  - BST=18 reduction stride.
//  Identical g_h layout, counters, polling (one per warp per step).
// -------------------------------------------------------------------------

namespace {
constexpr int B_      = 16;
constexpr int T_      = 2048;
constexpr int F_      = 128;
constexpr int U_      = 2048;
constexpr int GRID    = 128;
constexpr int THREADS = 512;
constexpr int COLS    = 16;
constexpr int NCHUNK  = 4;            // 4 chunks x 32 k per warp slice
constexpr int CHF     = 512;          // floats per chunk (32 k x 16 b)
constexpr int SLICE   = 2048;         // floats per warp slice
constexpr int BST     = 18;
constexpr int REDW    = COLS * BST;   // 288
constexpr int NZCAP   = 16;
}

// big scratch: precomputed input projection [t][n][b]
__device__ float g_u[T_ * U_ * B_];
// h triple buffer; within slice: [sub8][ic4][row2][g8][4]  (R9 layout)
__device__ __align__(16) float g_h[3][U_ * B_];
__device__ unsigned g_cnt[16 * 32];   // slice counters, 128B apart
__device__ unsigned g_ticket = 0;
// nonzero lists of input kernel columns
__device__ int   g_nzc[U_];
__device__ int   g_nzf[U_ * NZCAP];
__device__ float g_nzw[U_ * NZCAP];

struct SmemLayout {
  float Ws[U_ * COLS];       // 131072 B  [k][c]
  float sbuf[16][2][CHF];    //  65536 B  warp-private 2-slot rings (2KB each)
  float red[16 * REDW];      //  18432 B
  float wout_s[COLS];
  float ybuf[COLS * B_];
  unsigned base;
};
static_assert(sizeof(SmemLayout) <= 227 * 1024, "smem");

using u64 = unsigned long long;

__device__ __forceinline__ unsigned ld_acq(unsigned* p) {
  unsigned v;
  asm volatile("ld.acquire.gpu.global.u32 %0, [%1];" : "=r"(v) : "l"(p) : "memory");
  return v;
}
__device__ __forceinline__ void red_rel_add(unsigned* p) {
  asm volatile("red.release.gpu.global.add.u32 [%0], 1;" :: "l"(p) : "memory");
}
__device__ __forceinline__ void cpa16(uint32_t dst, const float* src) {
  asm volatile("cp.async.cg.shared.global [%0], [%1], 16;"
               :: "r"(dst), "l"(src) : "memory");
}
__device__ __forceinline__ u64 splat2(float w) {
  u64 r;
  asm("mov.b64 %0, {%1, %1};" : "=l"(r) : "r"(__float_as_uint(w)));
  return r;
}
__device__ __forceinline__ void fmax2(u64& a, u64 h, u64 w) {
  asm("fma.rn.f32x2 %0, %1, %2, %0;" : "+l"(a) : "l"(h), "l"(w));
}
__device__ __forceinline__ u64 addx2(u64 a, u64 b) {
  u64 r;
  asm("add.rn.f32x2 %0, %1, %2;" : "=l"(r) : "l"(a), "l"(b));
  return r;
}

// ---- setup kernel 1: nonzero lists per input-kernel column ----
__global__ void nz_kernel(const float* __restrict__ kern) {
  int n = blockIdx.x * blockDim.x + threadIdx.x;
  if (n >= U_) return;
  int cnt = 0;
  for (int f = 0; f < F_; ++f) {
    float v = kern[f * U_ + n];
    if (v != 0.f) {
      if (cnt < NZCAP) { g_nzw[n * NZCAP + cnt] = v; g_nzf[n * NZCAP + cnt] = f; }
      ++cnt;
    }
  }
  g_nzc[n] = cnt;
}

// ---- setup kernel 2: u[t][n][b] = bias[n] + sum_nz x[b][t][f]*w ----
__global__ void __launch_bounds__(512) uproj_kernel(
    const float* __restrict__ x, const float* __restrict__ kern,
    const float* __restrict__ bias) {
  __shared__ float sx[F_ * 20];  // [f][b], stride 20
  const int t = blockIdx.x;
  for (int i = threadIdx.x; i < B_ * F_; i += blockDim.x) {
    int b = i >> 7, f = i & 127;
    sx[f * 20 + b] = x[(b * T_ + t) * F_ + f];
  }
  __syncthreads();
  for (int it = threadIdx.x; it < U_ * 4; it += blockDim.x) {
    int n = it >> 2, bq = it & 3;
    float bs = bias[n];
    float4 acc = make_float4(bs, bs, bs, bs);
    int cnt = g_nzc[n];
    if (cnt <= NZCAP) {
      for (int i2 = 0; i2 < cnt; ++i2) {
        int f = g_nzf[n * NZCAP + i2];
        float w = g_nzw[n * NZCAP + i2];
        float4 xv = *reinterpret_cast<const float4*>(&sx[f * 20 + bq * 4]);
        acc.x += xv.x * w; acc.y += xv.y * w;
        acc.z += xv.z * w; acc.w += xv.w * w;
      }
    } else {
      for (int f = 0; f < F_; ++f) {
        float w = kern[f * U_ + n];
        float4 xv = *reinterpret_cast<const float4*>(&sx[f * 20 + bq * 4]);
        acc.x += xv.x * w; acc.y += xv.y * w;
        acc.z += xv.z * w; acc.w += xv.w * w;
      }
    }
    *reinterpret_cast<float4*>(&g_u[t * (U_ * B_) + n * B_ + bq * 4]) = acc;
  }
}

// ---- main persistent kernel ----
__global__ void __launch_bounds__(THREADS, 1) esn_kernel(
    const float* __restrict__ W,     // [U,U]
    const float* __restrict__ wout,  // [U,1]
    const float* __restrict__ bout,  // [1]
    float* __restrict__ out)         // [B,1]
{
  extern __shared__ unsigned char smem_raw[];
  SmemLayout& s = *reinterpret_cast<SmemLayout*>(smem_raw);
  const int tid  = threadIdx.x;
  const int n0   = blockIdx.x * COLS;
  const int lane = tid & 31;
  const int wrp  = tid >> 5;          // 0..15 = consumed slice id
  const int kk   = lane >> 3;
  const int hf   = (lane >> 2) & 1;
  const int q    = lane & 3;
  const int cS   = (tid >> 4) & 15;   // output col (tid<256)
  const int bS   = tid & 15;          // output batch

  if (blockIdx.x == 0 && tid < B_) out[tid] = bout[0];

  if (tid == 0) {
    unsigned tk = atomicAdd(&g_ticket, 1u);
    s.base = (tk / (unsigned)GRID) * (8u * (unsigned)T_);
  }

  for (int i = tid; i < U_ * COLS; i += THREADS) {
    int k = i >> 4, c = i & 15;
    s.Ws[i] = W[k * U_ + n0 + c];
  }
  if (tid < COLS) s.wout_s[tid] = wout[n0 + tid];
  __syncthreads();

  const unsigned base = s.base;

  // producer store index (permuted layout, identical to R9), constant over t
  int pidx = 0;
  if (tid < 256) {
    const int n = n0 + cS;
    pidx = (n >> 7) * SLICE + ((n >> 4) & 7) * 256 + ((n >> 2) & 3) * 64 +
           ((bS >> 2) & 1) * 32 + ((n & 3) * 2 + (bS >> 3)) * 4 + (bS & 3);
  }
  const float* uptr = g_u + (n0 + cS) * B_ + bS;

  // consumer constants
  float* const myring = &s.sbuf[wrp][0][0];
  const uint32_t rbase = (uint32_t)__cvta_generic_to_shared(myring);
  const int hoffB = (kk * 2 + hf) * 4;
  const float* const wbase = &s.Ws[(wrp * 128 + kk) * COLS + q * 4];
  unsigned* const mycnt = &g_cnt[wrp * 32];
  unsigned* const prodcnt = &g_cnt[(blockIdx.x >> 3) * 32];

  float hval = 0.f;

  for (int t = 0; t < T_; ++t) {
    // ---- u: one coalesced load, independent of h ----
    float uval = 0.f;
    if (tid < 256) uval = __ldg(uptr + t * (U_ * B_));

    float dot = 0.f;
    if (t > 0) {
      const unsigned tgt = base + 8u * (unsigned)t;
      while ((int)(ld_acq(mycnt) - tgt) < 0) {}

      const float* hsl = g_h[(t - 1) % 3] + wrp * SLICE;

      // prologue: chunk 0 into slot 0 (2KB = 4 cp.async per lane)
      #pragma unroll
      for (int j = 0; j < 4; ++j)
        cpa16(rbase + (unsigned)(j * 128 + lane * 4) * 4u,
              hsl + j * 128 + lane * 4);
      asm volatile("cp.async.commit_group;" ::: "memory");

      u64 acc[16];
      #pragma unroll
      for (int j = 0; j < 16; ++j) acc[j] = 0ull;

      #pragma unroll
      for (int c = 0; c < NCHUNK; ++c) {
        if (c + 1 < NCHUNK) {  // issue chunk c+1 into slot (c+1)&1
          const unsigned so = (unsigned)(((c + 1) & 1) * CHF) * 4u;
          const float* src = hsl + (c + 1) * CHF;
          #pragma unroll
          for (int j = 0; j < 4; ++j)
            cpa16(rbase + so + (unsigned)(j * 128 + lane * 4) * 4u,
                  src + j * 128 + lane * 4);
          asm volatile("cp.async.commit_group;" ::: "memory");
          asm volatile("cp.async.wait_group 1;" ::: "memory");
        } else {
          asm volatile("cp.async.wait_group 0;" ::: "memory");
        }
        __syncwarp();

        // chunk c = two 256-float sub-chunks in R9 layout
        #pragma unroll
        for (int half = 0; half < 2; ++half) {
          const float* hb = myring + (c & 1) * CHF + half * 256 + hoffB;
          const float* wc = wbase + (2 * c + half) * (16 * COLS);
          #pragma unroll
          for (int ic = 0; ic < 4; ++ic) {
            ulonglong2 ha  = *reinterpret_cast<const ulonglong2*>(hb + ic * 64);
            ulonglong2 hb2 = *reinterpret_cast<const ulonglong2*>(hb + ic * 64 + 32);
            const float4 wv = *reinterpret_cast<const float4*>(wc + ic * (4 * COLS));
            u64 w0 = splat2(wv.x), w1 = splat2(wv.y);
            u64 w2 = splat2(wv.z), w3 = splat2(wv.w);
            fmax2(acc[0],  ha.x,  w0); fmax2(acc[1],  ha.y,  w0);
            fmax2(acc[2],  hb2.x, w0); fmax2(acc[3],  hb2.y, w0);
            fmax2(acc[4],  ha.x,  w1); fmax2(acc[5],  ha.y,  w1);
            fmax2(acc[6],  hb2.x, w1); fmax2(acc[7],  hb2.y, w1);
            fmax2(acc[8],  ha.x,  w2); fmax2(acc[9],  ha.y,  w2);
            fmax2(acc[10], hb2.x, w2); fmax2(acc[11], hb2.y, w2);
            fmax2(acc[12], ha.x,  w3); fmax2(acc[13], ha.y,  w3);
            fmax2(acc[14], hb2.x, w3); fmax2(acc[15], hb2.y, w3);
          }
        }
        __syncwarp();  // all lanes done with slot before next-iter issue
      }

      // reduce over kk (lane bits 3,4); keeps (hf, q)
      #pragma unroll
      for (int j = 0; j < 16; ++j) {
        acc[j] = addx2(acc[j], __shfl_xor_sync(0xFFFFFFFFu, acc[j], 8));
        acc[j] = addx2(acc[j], __shfl_xor_sync(0xFFFFFFFFu, acc[j], 16));
      }
      if (kk == 0) {
        #pragma unroll
        for (int c = 0; c < 4; ++c) {
          float* r = &s.red[wrp * REDW + (4 * q + c) * BST + hf * 8];
          *reinterpret_cast<u64*>(r)     = acc[c * 4 + 0];
          *reinterpret_cast<u64*>(r + 2) = acc[c * 4 + 1];
          *reinterpret_cast<u64*>(r + 4) = acc[c * 4 + 2];
          *reinterpret_cast<u64*>(r + 6) = acc[c * 4 + 3];
        }
      }
      __syncthreads();

      if (tid < 256) {
        float sum = 0.f;
        const float* rp = &s.red[cS * BST + bS];
        #pragma unroll
        for (int g = 0; g < 16; ++g) sum += rp[g * REDW];
        dot = sum;
      }
    }

    // ---- tanh + store h ----
    if (tid < 256) {
      hval = tanhf(uval + dot);
      g_h[t % 3][pidx] = hval;
    }
    __syncthreads();
    if (tid == 0) red_rel_add(prodcnt);
  }

  // ---- readout ----
  if (tid < 256) s.ybuf[cS * B_ + bS] = hval * s.wout_s[cS];
  __syncthreads();
  if (tid < B_) {
    float y = 0.f;
    #pragma unroll
    for (int c = 0; c < COLS; ++c) y += s.ybuf[c * B_ + tid];
    atomicAdd(&out[tid], y);
  }
}

extern "C" void kernel_launch(void* const* d_in, const int* in_sizes, int n_in,
                              void* d_out, int out_size) {
  (void)in_sizes; (void)n_in; (void)out_size;
  const float* x    = (const float*)d_in[0];
  const float* kern = (const float*)d_in[1];
  const float* W    = (const float*)d_in[2];
  const float* bias = (const float*)d_in[3];
  const float* wout = (const float*)d_in[4];
  const float* bout = (const float*)d_in[5];

  nz_kernel<<<(U_ + 255) / 256, 256>>>(kern);
  uproj_kernel<<<T_, 512>>>(x, kern, bias);

  cudaFuncSetAttribute(esn_kernel, cudaFuncAttributeMaxDynamicSharedMemorySize,
                       (int)sizeof(SmemLayout));
  esn_kernel<<<GRID, THREADS, sizeof(SmemLayout)>>>(
      W, wout, bout, (float*)d_out);
}